// round 3
// baseline (speedup 1.0000x reference)
#include <cuda_runtime.h>
#include <math.h>
#include <stdint.h>

// ---- problem constants ----
#define BB    2
#define HIDN  2048
#define NHH   16
#define LLN   8
#define VV    32000
#define DDIM  128
#define OFFN  1024
#define RRES  1025
#define PHEAP 11272
#define NK    2049        // rows attended per (b,h) in every layer
#define FFN   8192
#define SSEQ  2048
#define NCHUNK 17         // ceil(NK/128)

// ---- device scratch (allocation-free) ----
__device__ __align__(16) float g_x [BB][HIDN];
__device__ __align__(16) float g_xn[BB][HIDN];
__device__ __align__(16) float g_q [BB][NHH][DDIM];
__device__ __align__(16) float g_kscr[LLN][BB][NHH][DDIM];
__device__ __align__(16) float g_vscr[LLN][BB][NHH][DDIM];
__device__ __align__(16) float g_scores[BB][NHH][NK];
__device__ float g_m  [BB][NHH];
__device__ float g_inv[BB][NHH];
__device__ __align__(16) float g_h[BB][FFN];
__device__ __align__(16) float g_opart[NCHUNK][BB][NHH][DDIM];

// ============================================================
// x = x + sinusoidal PE(pos)
// ============================================================
__global__ void k_init(const float* __restrict__ x, const int* __restrict__ posp) {
    int b = blockIdx.x;
    float pos = (float)(*posp);
    for (int e = threadIdx.x; e < HIDN; e += blockDim.x) {
        int i = e >> 1;
        float div = expf(-logf(10000.0f) * (2.0f * (float)i) / (float)HIDN);
        float ang = pos * div;
        float pe = (e & 1) ? cosf(ang) : sinf(ang);
        g_x[b][e] = x[(size_t)b * HIDN + e] + pe;
    }
}

// ============================================================
// xn = LN(x) * g + b   (two-pass, matching reference)
// ============================================================
__global__ void k_ln(const float* __restrict__ gam, const float* __restrict__ bet) {
    int b = blockIdx.x;
    int tid = threadIdx.x;               // 256 threads
    float vals[8];
    float s = 0.f;
    #pragma unroll
    for (int i = 0; i < 8; i++) { vals[i] = g_x[b][tid + i * 256]; s += vals[i]; }
    __shared__ float red[256];
    red[tid] = s; __syncthreads();
    for (int off = 128; off > 0; off >>= 1) { if (tid < off) red[tid] += red[tid + off]; __syncthreads(); }
    float mean = red[0] * (1.0f / HIDN);
    __syncthreads();
    float s2 = 0.f;
    #pragma unroll
    for (int i = 0; i < 8; i++) { float d = vals[i] - mean; s2 += d * d; }
    red[tid] = s2; __syncthreads();
    for (int off = 128; off > 0; off >>= 1) { if (tid < off) red[tid] += red[tid + off]; __syncthreads(); }
    float var = red[0] * (1.0f / HIDN);
    float rstd = rsqrtf(var + 1e-5f);
    #pragma unroll
    for (int i = 0; i < 8; i++) {
        int e = tid + i * 256;
        g_xn[b][e] = (vals[i] - mean) * rstd * gam[e] + bet[e];
    }
}

// ============================================================
// warp GEMV: one weight row, dots against both batch vectors
// ============================================================
__device__ __forceinline__ float2 warp_dot2(const float* __restrict__ w,
                                            const float* __restrict__ x0,
                                            const float* __restrict__ x1,
                                            int n4, int lane) {
    float a0 = 0.f, a1 = 0.f;
    const float4* w4 = (const float4*)w;
    const float4* p0 = (const float4*)x0;
    const float4* p1 = (const float4*)x1;
    #pragma unroll 4
    for (int i = lane; i < n4; i += 32) {
        float4 wv = w4[i];
        float4 u  = p0[i];
        float4 v  = p1[i];
        a0 += wv.x*u.x + wv.y*u.y + wv.z*u.z + wv.w*u.w;
        a1 += wv.x*v.x + wv.y*v.y + wv.z*v.z + wv.w*v.w;
    }
    #pragma unroll
    for (int off = 16; off > 0; off >>= 1) {
        a0 += __shfl_down_sync(0xffffffffu, a0, off);
        a1 += __shfl_down_sync(0xffffffffu, a1, off);
    }
    return make_float2(a0, a1);
}

// ============================================================
// QKV projection: 6144 rows of 2048; route to q / k-scratch / v-scratch
// ============================================================
__global__ void k_qkv(const float* __restrict__ qkv_w, int l) {
    int warp = threadIdx.x >> 5, lane = threadIdx.x & 31;
    int j = blockIdx.x * 8 + warp;                      // < 6144
    const float* w = qkv_w + ((size_t)l * 3 * HIDN + j) * HIDN;
    float2 r = warp_dot2(w, g_xn[0], g_xn[1], HIDN / 4, lane);
    if (lane == 0) {
        int h = j / 384, c = j % 384;
        #pragma unroll
        for (int b = 0; b < BB; b++) {
            float val = b ? r.y : r.x;
            if (c < 128)       g_q[b][h][c]              = val;
            else if (c < 256)  g_kscr[l][b][h][c - 128]  = val;
            else               g_vscr[l][b][h][c - 256]  = val;
        }
    }
}

// ============================================================
// KV row addressing with scatter-write overrides
//   layer 0      : heap rows [0,2049), row 2048 -> scratch[0]
//   layer l>=1   : rows [0,1025) -> heap[(l-1)*1025 + k]
//                  (row 1023 -> scratch[l-2] when l>=2)
//                  rows [1025,2049) -> off[l-1][...][k-1025]
// ============================================================
__device__ __forceinline__ const float* kv_row(int l, int b, int h, int k,
        const float* __restrict__ heap, const float* __restrict__ off,
        const float (*scr)[BB][NHH][DDIM]) {
    if (l == 0) {
        if (k == SSEQ) return scr[0][b][h];
        return heap + (((size_t)(b * NHH + h)) * PHEAP + (size_t)k) * DDIM;
    }
    if (k < RRES) {
        if (k == 1023 && l >= 2) return scr[l - 2][b][h];
        return heap + (((size_t)(b * NHH + h)) * PHEAP + (size_t)(l - 1) * RRES + (size_t)k) * DDIM;
    }
    return off + (((((size_t)(l - 1)) * BB + b) * NHH + h) * OFFN + (size_t)(k - RRES)) * DDIM;
}

// ============================================================
// attention scores: s[b,h,k] = q·K[k] / sqrt(D)
// grid (33, 32), block 256 (8 warps, each warp 8 rows)
// ============================================================
__global__ void k_scores(const float* __restrict__ k_heap, const float* __restrict__ k_off, int l) {
    int bh = blockIdx.y; int b = bh >> 4, h = bh & 15;
    int warp = threadIdx.x >> 5, lane = threadIdx.x & 31;
    __shared__ __align__(16) float qs[DDIM];
    if (threadIdx.x < DDIM) qs[threadIdx.x] = g_q[b][h][threadIdx.x];
    __syncthreads();
    float4 q4 = ((const float4*)qs)[lane];
    const float scale = 0.088388347648318447f;   // 1/sqrt(128)
    int base = blockIdx.x * 64;
    for (int r = warp; r < 64; r += 8) {
        int k = base + r;
        if (k >= NK) break;
        const float* kr = kv_row(l, b, h, k, k_heap, k_off, g_kscr);
        float4 kk = ((const float4*)kr)[lane];
        float s = q4.x*kk.x + q4.y*kk.y + q4.z*kk.z + q4.w*kk.w;
        #pragma unroll
        for (int off = 16; off > 0; off >>= 1) s += __shfl_down_sync(0xffffffffu, s, off);
        if (lane == 0) g_scores[b][h][k] = s * scale;
    }
}

// ============================================================
// per-(b,h) softmax stats: max and 1/sum(exp)
// ============================================================
__global__ void k_softstat() {
    int bh = blockIdx.x; int b = bh >> 4, h = bh & 15;
    int tid = threadIdx.x;               // 256
    __shared__ float red[256];
    float m = -1e30f;
    for (int k = tid; k < NK; k += 256) m = fmaxf(m, g_scores[b][h][k]);
    red[tid] = m; __syncthreads();
    for (int off = 128; off > 0; off >>= 1) { if (tid < off) red[tid] = fmaxf(red[tid], red[tid + off]); __syncthreads(); }
    float mb = red[0];
    __syncthreads();
    float s = 0.f;
    for (int k = tid; k < NK; k += 256) s += expf(g_scores[b][h][k] - mb);
    red[tid] = s; __syncthreads();
    for (int off = 128; off > 0; off >>= 1) { if (tid < off) red[tid] += red[tid + off]; __syncthreads(); }
    if (tid == 0) { g_m[b][h] = mb; g_inv[b][h] = 1.0f / red[0]; }
}

// ============================================================
// weighted V accumulate: per-chunk partials (deterministic, no atomics)
// grid (17, 32), block 128 (4 warps)
// ============================================================
__global__ void k_attnout(const float* __restrict__ v_heap, const float* __restrict__ v_off, int l) {
    int bh = blockIdx.y; int b = bh >> 4, h = bh & 15;
    int tid = threadIdx.x;               // 128
    int warp = tid >> 5, lane = tid & 31;
    __shared__ float a[128];
    __shared__ __align__(16) float red[4][DDIM];
    int base = blockIdx.x * 128;
    {
        int k = base + tid;
        float av = 0.f;
        if (k < NK) av = expf(g_scores[b][h][k] - g_m[b][h]) * g_inv[b][h];
        a[tid] = av;
    }
    __syncthreads();
    float4 acc = make_float4(0.f, 0.f, 0.f, 0.f);
    for (int r = warp; r < 128; r += 4) {
        int k = base + r;
        if (k >= NK) break;
        float av = a[r];
        const float* vr = kv_row(l, b, h, k, v_heap, v_off, g_vscr);
        float4 v4 = ((const float4*)vr)[lane];
        acc.x += av * v4.x; acc.y += av * v4.y; acc.z += av * v4.z; acc.w += av * v4.w;
    }
    ((float4*)red[warp])[lane] = acc;
    __syncthreads();
    if (tid < DDIM) {
        float s = red[0][tid] + red[1][tid] + red[2][tid] + red[3][tid];
        g_opart[blockIdx.x][b][h][tid] = s;
    }
}

// combine partial chunks into residual stream: x += attn_out
__global__ void k_combine() {
    int bh = blockIdx.x; int b = bh >> 4, h = bh & 15;
    int t = threadIdx.x;                 // 128
    float s = 0.f;
    #pragma unroll
    for (int c = 0; c < NCHUNK; c++) s += g_opart[c][b][h][t];
    g_x[b][h * DDIM + t] += s;
}

// ============================================================
// FFN
// ============================================================
__device__ __forceinline__ float gelu_exact(float x) {
    return 0.5f * x * (1.0f + erff(x * 0.70710678118654752f));
}

__global__ void k_ffn1(const float* __restrict__ w, int l) {
    int warp = threadIdx.x >> 5, lane = threadIdx.x & 31;
    int j = blockIdx.x * 8 + warp;                      // < 8192
    const float* row = w + ((size_t)l * FFN + j) * HIDN;
    float2 r = warp_dot2(row, g_xn[0], g_xn[1], HIDN / 4, lane);
    if (lane == 0) { g_h[0][j] = gelu_exact(r.x); g_h[1][j] = gelu_exact(r.y); }
}

__global__ void k_ffn2(const float* __restrict__ w, int l) {
    int warp = threadIdx.x >> 5, lane = threadIdx.x & 31;
    int j = blockIdx.x * 8 + warp;                      // < 2048
    const float* row = w + ((size_t)l * HIDN + j) * FFN;
    float2 r = warp_dot2(row, g_h[0], g_h[1], FFN / 4, lane);
    if (lane == 0) { g_x[0][j] += r.x; g_x[1][j] += r.y; }
}

// ============================================================
// LM head + final softmax
// ============================================================
__global__ void k_lmhead(const float* __restrict__ w, float* __restrict__ out) {
    int warp = threadIdx.x >> 5, lane = threadIdx.x & 31;
    int j = blockIdx.x * 8 + warp;                      // < 32000
    const float* row = w + (size_t)j * HIDN;
    float2 r = warp_dot2(row, g_xn[0], g_xn[1], HIDN / 4, lane);
    if (lane == 0) { out[j] = r.x; out[(size_t)VV + j] = r.y; }
}

__global__ void k_softmax(float* __restrict__ out) {
    int b = blockIdx.x;
    float* o = out + (size_t)b * VV;
    int tid = threadIdx.x;               // 1024
    __shared__ float red[1024];
    float m = -1e30f;
    for (int i = tid; i < VV; i += 1024) m = fmaxf(m, o[i]);
    red[tid] = m; __syncthreads();
    for (int off = 512; off > 0; off >>= 1) { if (tid < off) red[tid] = fmaxf(red[tid], red[tid + off]); __syncthreads(); }
    float mb = red[0];
    __syncthreads();
    float s = 0.f;
    for (int i = tid; i < VV; i += 1024) s += expf(o[i] - mb);
    red[tid] = s; __syncthreads();
    for (int off = 512; off > 0; off >>= 1) { if (tid < off) red[tid] += red[tid + off]; __syncthreads(); }
    float inv = 1.0f / red[0];
    __syncthreads();
    for (int i = tid; i < VV; i += 1024) o[i] = expf(o[i] - mb) * inv;
}

// ============================================================
// launch (graph-capturable: kernel launches only)
// ============================================================
extern "C" void kernel_launch(void* const* d_in, const int* in_sizes, int n_in,
                              void* d_out, int out_size) {
    const float* x      = (const float*)d_in[0];
    const float* qkv_w  = (const float*)d_in[1];
    const float* ffn1_w = (const float*)d_in[2];
    const float* ffn2_w = (const float*)d_in[3];
    const float* out_w  = (const float*)d_in[4];
    const float* ln_g   = (const float*)d_in[5];
    const float* ln_b   = (const float*)d_in[6];
    const float* k_heap = (const float*)d_in[7];
    const float* v_heap = (const float*)d_in[8];
    const float* k_off  = (const float*)d_in[9];
    const float* v_off  = (const float*)d_in[10];
    const int*   pos    = (const int*)  d_in[11];
    float* out = (float*)d_out;

    k_init<<<BB, 256>>>(x, pos);

    for (int l = 0; l < LLN; l++) {
        k_ln<<<BB, 256>>>(ln_g, ln_b);
        k_qkv<<<768, 256>>>(qkv_w, l);
        { dim3 gs(33, BB * NHH); k_scores<<<gs, 256>>>(k_heap, k_off, l); }
        k_softstat<<<BB * NHH, 256>>>();
        { dim3 go(NCHUNK, BB * NHH); k_attnout<<<go, 128>>>(v_heap, v_off, l); }
        k_combine<<<BB * NHH, 128>>>();
        k_ln<<<BB, 256>>>(ln_g, ln_b);
        k_ffn1<<<1024, 256>>>(ffn1_w, l);
        k_ffn2<<<256, 256>>>(ffn2_w, l);
    }

    k_ln<<<BB, 256>>>(ln_g, ln_b);
    k_lmhead<<<4000, 256>>>(out_w, out);
    k_softmax<<<BB, 1024>>>(out);
}

// round 4
// speedup vs baseline: 1.1675x; 1.1675x over previous
#include <cuda_runtime.h>
#include <math.h>
#include <stdint.h>

// ---- problem constants ----
#define BB    2
#define HIDN  2048
#define NHH   16
#define LLN   8
#define VV    32000
#define DDIM  128
#define OFFN  1024
#define RRES  1025
#define PHEAP 11272
#define NK    2049
#define FFN   8192
#define SSEQ  2048
#define NCHUNK 17

// ---- device scratch (allocation-free) ----
__device__ __align__(16) float g_x [BB][HIDN];
__device__ __align__(16) float g_q [BB][NHH][DDIM];
__device__ __align__(16) float g_kscr[LLN][BB][NHH][DDIM];
__device__ __align__(16) float g_vscr[LLN][BB][NHH][DDIM];
__device__ __align__(16) float g_h[BB][FFN];
__device__ float g_pm[NCHUNK][BB * NHH];
__device__ float g_ps[NCHUNK][BB * NHH];
__device__ __align__(16) float g_po[NCHUNK][BB * NHH][DDIM];

// ============================================================
// x = x + sinusoidal PE(pos)
// ============================================================
__global__ void k_init(const float* __restrict__ x, const int* __restrict__ posp) {
    int b = blockIdx.x;
    float pos = (float)(*posp);
    for (int e = threadIdx.x; e < HIDN; e += blockDim.x) {
        int i = e >> 1;
        float div = expf(-logf(10000.0f) * (2.0f * (float)i) / (float)HIDN);
        float ang = pos * div;
        float pe = (e & 1) ? cosf(ang) : sinf(ang);
        g_x[b][e] = x[(size_t)b * HIDN + e] + pe;
    }
}

// ============================================================
// LN prologue: stage LN(g_x)*g+b for BOTH batches into smem.
// xs layout: [0,512) = batch0 float4, [512,1024) = batch1 float4.
// block must be 256 threads.
// ============================================================
__device__ __forceinline__ void stage_ln(float4* xs,
                                         const float* __restrict__ gam,
                                         const float* __restrict__ bet,
                                         float4* red4) {
    int tid = threadIdx.x;
    const float4* x0 = (const float4*)g_x[0];
    const float4* x1 = (const float4*)g_x[1];
    float4 a0 = x0[tid], a1 = x0[tid + 256];
    float4 b0 = x1[tid], b1 = x1[tid + 256];
    float s0 = a0.x + a0.y + a0.z + a0.w + a1.x + a1.y + a1.z + a1.w;
    float s1 = b0.x + b0.y + b0.z + b0.w + b1.x + b1.y + b1.z + b1.w;
    float q0 = a0.x*a0.x + a0.y*a0.y + a0.z*a0.z + a0.w*a0.w
             + a1.x*a1.x + a1.y*a1.y + a1.z*a1.z + a1.w*a1.w;
    float q1 = b0.x*b0.x + b0.y*b0.y + b0.z*b0.z + b0.w*b0.w
             + b1.x*b1.x + b1.y*b1.y + b1.z*b1.z + b1.w*b1.w;
    red4[tid] = make_float4(s0, q0, s1, q1);
    __syncthreads();
    for (int off = 128; off > 0; off >>= 1) {
        if (tid < off) {
            float4 u = red4[tid], v = red4[tid + off];
            red4[tid] = make_float4(u.x + v.x, u.y + v.y, u.z + v.z, u.w + v.w);
        }
        __syncthreads();
    }
    float4 tot = red4[0];
    float mean0 = tot.x * (1.0f / HIDN);
    float mean1 = tot.z * (1.0f / HIDN);
    float var0  = tot.y * (1.0f / HIDN) - mean0 * mean0;
    float var1  = tot.w * (1.0f / HIDN) - mean1 * mean1;
    float r0 = rsqrtf(var0 + 1e-5f);
    float r1 = rsqrtf(var1 + 1e-5f);
    const float4* g4 = (const float4*)gam;
    const float4* e4 = (const float4*)bet;
    float4 ga = g4[tid], gb = g4[tid + 256];
    float4 ea = e4[tid], eb = e4[tid + 256];
    xs[tid] = make_float4((a0.x - mean0) * r0 * ga.x + ea.x,
                          (a0.y - mean0) * r0 * ga.y + ea.y,
                          (a0.z - mean0) * r0 * ga.z + ea.z,
                          (a0.w - mean0) * r0 * ga.w + ea.w);
    xs[tid + 256] = make_float4((a1.x - mean0) * r0 * gb.x + eb.x,
                                (a1.y - mean0) * r0 * gb.y + eb.y,
                                (a1.z - mean0) * r0 * gb.z + eb.z,
                                (a1.w - mean0) * r0 * gb.w + eb.w);
    xs[512 + tid] = make_float4((b0.x - mean1) * r1 * ga.x + ea.x,
                                (b0.y - mean1) * r1 * ga.y + ea.y,
                                (b0.z - mean1) * r1 * ga.z + ea.z,
                                (b0.w - mean1) * r1 * ga.w + ea.w);
    xs[512 + tid + 256] = make_float4((b1.x - mean1) * r1 * gb.x + eb.x,
                                      (b1.y - mean1) * r1 * gb.y + eb.y,
                                      (b1.z - mean1) * r1 * gb.z + eb.z,
                                      (b1.w - mean1) * r1 * gb.w + eb.w);
    __syncthreads();
}

// warp GEMV: one weight row (gmem stream only) vs two smem vectors
template <int N4>
__device__ __forceinline__ float2 dot2_smem(const float4* __restrict__ w4,
                                            const float4* xs, int lane) {
    float a0 = 0.f, a1 = 0.f;
    #pragma unroll 8
    for (int i = lane; i < N4; i += 32) {
        float4 wv = w4[i];
        float4 u = xs[i];
        float4 v = xs[N4 + i];
        a0 += wv.x*u.x + wv.y*u.y + wv.z*u.z + wv.w*u.w;
        a1 += wv.x*v.x + wv.y*v.y + wv.z*v.z + wv.w*v.w;
    }
    #pragma unroll
    for (int off = 16; off > 0; off >>= 1) {
        a0 += __shfl_down_sync(0xffffffffu, a0, off);
        a1 += __shfl_down_sync(0xffffffffu, a1, off);
    }
    return make_float2(a0, a1);
}

// ============================================================
// QKV projection (LN fused): 6144 rows, route q/k/v
// ============================================================
__global__ void k_qkv(const float* __restrict__ qkv_w,
                      const float* __restrict__ gam, const float* __restrict__ bet, int l) {
    __shared__ __align__(16) float4 xs[1024];
    __shared__ __align__(16) float4 red4[256];
    stage_ln(xs, gam, bet, red4);
    int warp = threadIdx.x >> 5, lane = threadIdx.x & 31;
    int j = blockIdx.x * 8 + warp;
    const float4* w4 = (const float4*)(qkv_w + ((size_t)l * 3 * HIDN + j) * HIDN);
    float2 r = dot2_smem<512>(w4, xs, lane);
    if (lane == 0) {
        int h = j / 384, c = j % 384;
        #pragma unroll
        for (int b = 0; b < BB; b++) {
            float val = b ? r.y : r.x;
            if (c < 128)      g_q[b][h][c]             = val;
            else if (c < 256) g_kscr[l][b][h][c - 128] = val;
            else              g_vscr[l][b][h][c - 256] = val;
        }
    }
}

// ============================================================
// KV row addressing with scatter-write overrides
// ============================================================
__device__ __forceinline__ const float* kv_row(int l, int b, int h, int k,
        const float* __restrict__ heap, const float* __restrict__ off,
        const float (*scr)[BB][NHH][DDIM]) {
    if (l == 0) {
        if (k == SSEQ) return scr[0][b][h];
        return heap + (((size_t)(b * NHH + h)) * PHEAP + (size_t)k) * DDIM;
    }
    if (k < RRES) {
        if (k == 1023 && l >= 2) return scr[l - 2][b][h];
        return heap + (((size_t)(b * NHH + h)) * PHEAP + (size_t)(l - 1) * RRES + (size_t)k) * DDIM;
    }
    return off + (((((size_t)(l - 1)) * BB + b) * NHH + h) * OFFN + (size_t)(k - RRES)) * DDIM;
}

// ============================================================
// fused flash-decode partial: one chunk of 128 KV rows per block
// K dots via smem transpose (no shfl chains), local softmax, V accum
// grid (17, 32), block 256
// ============================================================
__global__ void k_flash(const float* __restrict__ kh, const float* __restrict__ ko,
                        const float* __restrict__ vh, const float* __restrict__ vo, int l) {
    int bh = blockIdx.y; int b = bh >> 4, h = bh & 15;
    int base = blockIdx.x * 128;
    int tid = threadIdx.x, warp = tid >> 5, lane = tid & 31;
    __shared__ float part[128][33];
    __shared__ float sc[128];
    __shared__ float red[128];
    __shared__ __align__(16) float4 vred[8][32];
    __shared__ __align__(16) float q_s[DDIM];
    if (tid < DDIM) q_s[tid] = g_q[b][h][tid];
    __syncthreads();
    float4 q4 = ((const float4*)q_s)[lane];

    // ---- K phase: warp handles 16 independent rows ----
    #pragma unroll 4
    for (int i = 0; i < 16; i++) {
        int r = warp * 16 + i, k = base + r;
        float p = 0.f;
        if (k < NK) {
            const float* kr = kv_row(l, b, h, k, kh, ko, g_kscr);
            float4 kk = ((const float4*)kr)[lane];
            p = q4.x*kk.x + q4.y*kk.y + q4.z*kk.z + q4.w*kk.w;
        }
        part[r][lane] = p;
    }
    __syncthreads();

    // ---- score reduce (conflict-free, stride 33) ----
    if (tid < 128) {
        float s = 0.f;
        #pragma unroll
        for (int i = 0; i < 32; i++) s += part[tid][i];
        s *= 0.088388347648318447f;
        if (base + tid >= NK) s = -1e30f;
        sc[tid] = s;
    }
    __syncthreads();
    // block max over 128
    if (tid < 64) red[tid] = fmaxf(sc[tid], sc[tid + 64]);
    __syncthreads();
    if (tid < 32) red[tid] = fmaxf(red[tid], red[tid + 32]);
    __syncthreads();
    if (tid < 16) red[tid] = fmaxf(red[tid], red[tid + 16]);
    __syncthreads();
    if (tid < 8)  red[tid] = fmaxf(red[tid], red[tid + 8]);
    __syncthreads();
    if (tid < 4)  red[tid] = fmaxf(red[tid], red[tid + 4]);
    __syncthreads();
    if (tid < 2)  red[tid] = fmaxf(red[tid], red[tid + 2]);
    __syncthreads();
    if (tid == 0) red[0] = fmaxf(red[0], red[1]);
    __syncthreads();
    float mloc = red[0];
    __syncthreads();
    if (tid < 128) sc[tid] = expf(sc[tid] - mloc);   // invalid rows -> 0
    __syncthreads();
    // block sum over 128
    if (tid < 64) red[tid] = sc[tid] + sc[tid + 64];
    __syncthreads();
    if (tid < 32) red[tid] += red[tid + 32];
    __syncthreads();
    if (tid < 16) red[tid] += red[tid + 16];
    __syncthreads();
    if (tid < 8)  red[tid] += red[tid + 8];
    __syncthreads();
    if (tid < 4)  red[tid] += red[tid + 4];
    __syncthreads();
    if (tid < 2)  red[tid] += red[tid + 2];
    __syncthreads();
    if (tid == 0) red[0] += red[1];
    __syncthreads();
    float ssum = red[0];

    // ---- V phase ----
    float4 acc = make_float4(0.f, 0.f, 0.f, 0.f);
    #pragma unroll 4
    for (int i = 0; i < 16; i++) {
        int r = warp * 16 + i, k = base + r;
        if (k < NK) {
            const float* vr = kv_row(l, b, h, k, vh, vo, g_vscr);
            float4 v4 = ((const float4*)vr)[lane];
            float pr = sc[r];
            acc.x += pr * v4.x; acc.y += pr * v4.y;
            acc.z += pr * v4.z; acc.w += pr * v4.w;
        }
    }
    vred[warp][lane] = acc;
    __syncthreads();
    if (tid < 128) {
        int li = tid >> 2, c = tid & 3;
        float o = 0.f;
        #pragma unroll
        for (int w2 = 0; w2 < 8; w2++) o += ((const float*)&vred[w2][li])[c];
        g_po[blockIdx.x][bh][tid] = o;
    }
    if (tid == 0) { g_pm[blockIdx.x][bh] = mloc; g_ps[blockIdx.x][bh] = ssum; }
}

// combine partial chunks: x += softmax-weighted V  (grid 32, block 128)
__global__ void k_comb() {
    int bh = blockIdx.x; int b = bh >> 4, h = bh & 15;
    int t = threadIdx.x;
    float m = -1e30f;
    #pragma unroll
    for (int c = 0; c < NCHUNK; c++) m = fmaxf(m, g_pm[c][bh]);
    float S = 0.f, o = 0.f;
    #pragma unroll
    for (int c = 0; c < NCHUNK; c++) {
        float w = expf(g_pm[c][bh] - m);
        S += g_ps[c][bh] * w;
        o += g_po[c][bh][t] * w;
    }
    g_x[b][h * DDIM + t] += o / S;
}

// ============================================================
// FFN
// ============================================================
__device__ __forceinline__ float gelu_exact(float x) {
    return 0.5f * x * (1.0f + erff(x * 0.70710678118654752f));
}

__global__ void k_ffn1(const float* __restrict__ w,
                       const float* __restrict__ gam, const float* __restrict__ bet, int l) {
    __shared__ __align__(16) float4 xs[1024];
    __shared__ __align__(16) float4 red4[256];
    stage_ln(xs, gam, bet, red4);
    int warp = threadIdx.x >> 5, lane = threadIdx.x & 31;
    int j = blockIdx.x * 8 + warp;
    const float4* w4 = (const float4*)(w + ((size_t)l * FFN + j) * HIDN);
    float2 r = dot2_smem<512>(w4, xs, lane);
    if (lane == 0) { g_h[0][j] = gelu_exact(r.x); g_h[1][j] = gelu_exact(r.y); }
}

__global__ void k_ffn2(const float* __restrict__ w, int l) {
    extern __shared__ float4 hs[];           // 4096 float4 = 64KB (both batches)
    const float4* hsrc = (const float4*)g_h[0];
    for (int i = threadIdx.x; i < 4096; i += 256) hs[i] = hsrc[i];
    __syncthreads();
    int warp = threadIdx.x >> 5, lane = threadIdx.x & 31;
    int j = blockIdx.x * 8 + warp;
    const float4* w4 = (const float4*)(w + ((size_t)l * HIDN + j) * FFN);
    float2 r = dot2_smem<2048>(w4, hs, lane);
    if (lane == 0) { g_x[0][j] += r.x; g_x[1][j] += r.y; }
}

// ============================================================
// LM head (LN fused) + final softmax
// ============================================================
__global__ void k_lmhead(const float* __restrict__ w,
                         const float* __restrict__ gam, const float* __restrict__ bet,
                         float* __restrict__ out) {
    __shared__ __align__(16) float4 xs[1024];
    __shared__ __align__(16) float4 red4[256];
    stage_ln(xs, gam, bet, red4);
    int warp = threadIdx.x >> 5, lane = threadIdx.x & 31;
    int j = blockIdx.x * 8 + warp;
    const float4* w4 = (const float4*)(w + (size_t)j * HIDN);
    float2 r = dot2_smem<512>(w4, xs, lane);
    if (lane == 0) { out[j] = r.x; out[(size_t)VV + j] = r.y; }
}

__global__ void k_softmax(float* __restrict__ out) {
    int b = blockIdx.x;
    float* o = out + (size_t)b * VV;
    int tid = threadIdx.x;               // 1024
    __shared__ float red[1024];
    float m = -1e30f;
    for (int i = tid; i < VV; i += 1024) m = fmaxf(m, o[i]);
    red[tid] = m; __syncthreads();
    for (int off = 512; off > 0; off >>= 1) { if (tid < off) red[tid] = fmaxf(red[tid], red[tid + off]); __syncthreads(); }
    float mb = red[0];
    __syncthreads();
    float s = 0.f;
    for (int i = tid; i < VV; i += 1024) s += expf(o[i] - mb);
    red[tid] = s; __syncthreads();
    for (int off = 512; off > 0; off >>= 1) { if (tid < off) red[tid] += red[tid + off]; __syncthreads(); }
    float inv = 1.0f / red[0];
    __syncthreads();
    for (int i = tid; i < VV; i += 1024) o[i] = expf(o[i] - mb) * inv;
}

// ============================================================
// launch (graph-capturable: kernel launches only)
// ============================================================
extern "C" void kernel_launch(void* const* d_in, const int* in_sizes, int n_in,
                              void* d_out, int out_size) {
    const float* x      = (const float*)d_in[0];
    const float* qkv_w  = (const float*)d_in[1];
    const float* ffn1_w = (const float*)d_in[2];
    const float* ffn2_w = (const float*)d_in[3];
    const float* out_w  = (const float*)d_in[4];
    const float* ln_g   = (const float*)d_in[5];
    const float* ln_b   = (const float*)d_in[6];
    const float* k_heap = (const float*)d_in[7];
    const float* v_heap = (const float*)d_in[8];
    const float* k_off  = (const float*)d_in[9];
    const float* v_off  = (const float*)d_in[10];
    const int*   pos    = (const int*)  d_in[11];
    float* out = (float*)d_out;

    cudaFuncSetAttribute(k_ffn2, cudaFuncAttributeMaxDynamicSharedMemorySize, 65536);

    k_init<<<BB, 256>>>(x, pos);

    for (int l = 0; l < LLN; l++) {
        k_qkv<<<768, 256>>>(qkv_w, ln_g, ln_b, l);
        { dim3 gs(NCHUNK, BB * NHH); k_flash<<<gs, 256>>>(k_heap, k_off, v_heap, v_off, l); }
        k_comb<<<BB * NHH, 128>>>();
        k_ffn1<<<1024, 256>>>(ffn1_w, ln_g, ln_b, l);
        k_ffn2<<<256, 256, 65536>>>(ffn2_w, l);
    }

    k_lmhead<<<4000, 256>>>(out_w, ln_g, ln_b, out);
    k_softmax<<<BB, 1024>>>(out);
}

// round 5
// speedup vs baseline: 1.2206x; 1.0455x over previous
#include <cuda_runtime.h>
#include <math.h>
#include <stdint.h>

// ---- problem constants ----
#define BB    2
#define HIDN  2048
#define NHH   16
#define LLN   8
#define VV    32000
#define DDIM  128
#define OFFN  1024
#define RRES  1025
#define PHEAP 11272
#define NK    2049
#define FFN   8192
#define SSEQ  2048
#define NCHUNK 17

// ---- device scratch (allocation-free) ----
__device__ __align__(16) float g_x [BB][HIDN];
__device__ __align__(16) float g_q [BB][NHH][DDIM];
__device__ __align__(16) float g_kscr[LLN][BB][NHH][DDIM];
__device__ __align__(16) float g_vscr[LLN][BB][NHH][DDIM];
__device__ __align__(16) float g_h[BB][FFN];
__device__ float g_pm[NCHUNK][BB * NHH];
__device__ float g_ps[NCHUNK][BB * NHH];
__device__ __align__(16) float g_po[NCHUNK][BB * NHH][DDIM];
__device__ unsigned int g_cnt[BB * NHH];   // zero-init; self-resetting

// ============================================================
// x = x + sinusoidal PE(pos)
// ============================================================
__global__ void k_init(const float* __restrict__ x, const int* __restrict__ posp) {
    int b = blockIdx.x;
    float pos = (float)(*posp);
    for (int e = threadIdx.x; e < HIDN; e += blockDim.x) {
        int i = e >> 1;
        float div = expf(-logf(10000.0f) * (2.0f * (float)i) / (float)HIDN);
        float ang = pos * div;
        float pe = (e & 1) ? cosf(ang) : sinf(ang);
        g_x[b][e] = x[(size_t)b * HIDN + e] + pe;
    }
}

// ============================================================
// LN prologue (warp-shuffle version, 3 barriers).
// xs layout: [0,512) = batch0 float4, [512,1024) = batch1 float4.
// block must be 256 threads.
// ============================================================
__device__ __forceinline__ void stage_ln(float4* xs,
                                         const float* __restrict__ gam,
                                         const float* __restrict__ bet) {
    int tid = threadIdx.x, lane = tid & 31, warp = tid >> 5;
    __shared__ float4 wred[8];
    __shared__ float4 stats;   // mean0, rstd0, mean1, rstd1
    const float4* x0 = (const float4*)g_x[0];
    const float4* x1 = (const float4*)g_x[1];
    float4 a0 = x0[tid], a1 = x0[tid + 256];
    float4 b0 = x1[tid], b1 = x1[tid + 256];
    float s0 = a0.x + a0.y + a0.z + a0.w + a1.x + a1.y + a1.z + a1.w;
    float s1 = b0.x + b0.y + b0.z + b0.w + b1.x + b1.y + b1.z + b1.w;
    float q0 = a0.x*a0.x + a0.y*a0.y + a0.z*a0.z + a0.w*a0.w
             + a1.x*a1.x + a1.y*a1.y + a1.z*a1.z + a1.w*a1.w;
    float q1 = b0.x*b0.x + b0.y*b0.y + b0.z*b0.z + b0.w*b0.w
             + b1.x*b1.x + b1.y*b1.y + b1.z*b1.z + b1.w*b1.w;
    #pragma unroll
    for (int off = 16; off > 0; off >>= 1) {
        s0 += __shfl_down_sync(0xffffffffu, s0, off);
        q0 += __shfl_down_sync(0xffffffffu, q0, off);
        s1 += __shfl_down_sync(0xffffffffu, s1, off);
        q1 += __shfl_down_sync(0xffffffffu, q1, off);
    }
    if (lane == 0) wred[warp] = make_float4(s0, q0, s1, q1);
    __syncthreads();
    if (warp == 0) {
        float4 v = wred[lane & 7];
        float t0 = v.x, t1 = v.y, t2 = v.z, t3 = v.w;
        #pragma unroll
        for (int off = 4; off > 0; off >>= 1) {
            t0 += __shfl_down_sync(0xffffffffu, t0, off, 8);
            t1 += __shfl_down_sync(0xffffffffu, t1, off, 8);
            t2 += __shfl_down_sync(0xffffffffu, t2, off, 8);
            t3 += __shfl_down_sync(0xffffffffu, t3, off, 8);
        }
        if (lane == 0) {
            float mean0 = t0 * (1.0f / HIDN);
            float mean1 = t2 * (1.0f / HIDN);
            float var0  = t1 * (1.0f / HIDN) - mean0 * mean0;
            float var1  = t3 * (1.0f / HIDN) - mean1 * mean1;
            stats = make_float4(mean0, rsqrtf(var0 + 1e-5f),
                                mean1, rsqrtf(var1 + 1e-5f));
        }
    }
    __syncthreads();
    float4 st = stats;
    const float4* g4 = (const float4*)gam;
    const float4* e4 = (const float4*)bet;
    float4 ga = g4[tid], gb = g4[tid + 256];
    float4 ea = e4[tid], eb = e4[tid + 256];
    xs[tid] = make_float4((a0.x - st.x) * st.y * ga.x + ea.x,
                          (a0.y - st.x) * st.y * ga.y + ea.y,
                          (a0.z - st.x) * st.y * ga.z + ea.z,
                          (a0.w - st.x) * st.y * ga.w + ea.w);
    xs[tid + 256] = make_float4((a1.x - st.x) * st.y * gb.x + eb.x,
                                (a1.y - st.x) * st.y * gb.y + eb.y,
                                (a1.z - st.x) * st.y * gb.z + eb.z,
                                (a1.w - st.x) * st.y * gb.w + eb.w);
    xs[512 + tid] = make_float4((b0.x - st.z) * st.w * ga.x + ea.x,
                                (b0.y - st.z) * st.w * ga.y + ea.y,
                                (b0.z - st.z) * st.w * ga.z + ea.z,
                                (b0.w - st.z) * st.w * ga.w + ea.w);
    xs[512 + tid + 256] = make_float4((b1.x - st.z) * st.w * gb.x + eb.x,
                                      (b1.y - st.z) * st.w * gb.y + eb.y,
                                      (b1.z - st.z) * st.w * gb.z + eb.z,
                                      (b1.w - st.z) * st.w * gb.w + eb.w);
    __syncthreads();
}

// warp GEMV: one weight row (gmem stream only) vs two smem vectors
template <int N4>
__device__ __forceinline__ float2 dot2_smem(const float4* __restrict__ w4,
                                            const float4* xs, int lane) {
    float a0 = 0.f, a1 = 0.f;
    #pragma unroll 8
    for (int i = lane; i < N4; i += 32) {
        float4 wv = w4[i];
        float4 u = xs[i];
        float4 v = xs[N4 + i];
        a0 += wv.x*u.x + wv.y*u.y + wv.z*u.z + wv.w*u.w;
        a1 += wv.x*v.x + wv.y*v.y + wv.z*v.z + wv.w*v.w;
    }
    #pragma unroll
    for (int off = 16; off > 0; off >>= 1) {
        a0 += __shfl_down_sync(0xffffffffu, a0, off);
        a1 += __shfl_down_sync(0xffffffffu, a1, off);
    }
    return make_float2(a0, a1);
}

// ============================================================
// QKV projection (LN fused): 6144 rows, route q/k/v
// ============================================================
__global__ void k_qkv(const float* __restrict__ qkv_w,
                      const float* __restrict__ gam, const float* __restrict__ bet, int l) {
    __shared__ __align__(16) float4 xs[1024];
    stage_ln(xs, gam, bet);
    int warp = threadIdx.x >> 5, lane = threadIdx.x & 31;
    int j = blockIdx.x * 8 + warp;
    const float4* w4 = (const float4*)(qkv_w + ((size_t)l * 3 * HIDN + j) * HIDN);
    float2 r = dot2_smem<512>(w4, xs, lane);
    if (lane == 0) {
        int h = j / 384, c = j % 384;
        #pragma unroll
        for (int b = 0; b < BB; b++) {
            float val = b ? r.y : r.x;
            if (c < 128)      g_q[b][h][c]             = val;
            else if (c < 256) g_kscr[l][b][h][c - 128] = val;
            else              g_vscr[l][b][h][c - 256] = val;
        }
    }
}

// ============================================================
// KV row addressing with scatter-write overrides
// ============================================================
__device__ __forceinline__ const float* kv_row(int l, int b, int h, int k,
        const float* __restrict__ heap, const float* __restrict__ off,
        const float (*scr)[BB][NHH][DDIM]) {
    if (l == 0) {
        if (k == SSEQ) return scr[0][b][h];
        return heap + (((size_t)(b * NHH + h)) * PHEAP + (size_t)k) * DDIM;
    }
    if (k < RRES) {
        if (k == 1023 && l >= 2) return scr[l - 2][b][h];
        return heap + (((size_t)(b * NHH + h)) * PHEAP + (size_t)(l - 1) * RRES + (size_t)k) * DDIM;
    }
    return off + (((((size_t)(l - 1)) * BB + b) * NHH + h) * OFFN + (size_t)(k - RRES)) * DDIM;
}

// ============================================================
// fused flash-decode partial + last-block combine
// grid (17, 32), block 256
// ============================================================
__global__ void k_flash(const float* __restrict__ kh, const float* __restrict__ ko,
                        const float* __restrict__ vh, const float* __restrict__ vo, int l) {
    int bh = blockIdx.y; int b = bh >> 4, h = bh & 15;
    int base = blockIdx.x * 128;
    int tid = threadIdx.x, warp = tid >> 5, lane = tid & 31;
    __shared__ float part[128][33];
    __shared__ float sc[128];
    __shared__ float red[128];
    __shared__ __align__(16) float4 vred[8][32];
    __shared__ __align__(16) float q_s[DDIM];
    __shared__ bool is_last;
    if (tid < DDIM) q_s[tid] = g_q[b][h][tid];
    __syncthreads();
    float4 q4 = ((const float4*)q_s)[lane];

    // ---- K phase: warp handles 16 independent rows ----
    #pragma unroll 4
    for (int i = 0; i < 16; i++) {
        int r = warp * 16 + i, k = base + r;
        float p = 0.f;
        if (k < NK) {
            const float* kr = kv_row(l, b, h, k, kh, ko, g_kscr);
            float4 kk = ((const float4*)kr)[lane];
            p = q4.x*kk.x + q4.y*kk.y + q4.z*kk.z + q4.w*kk.w;
        }
        part[r][lane] = p;
    }
    __syncthreads();

    // ---- score reduce (conflict-free, stride 33) ----
    if (tid < 128) {
        float s = 0.f;
        #pragma unroll
        for (int i = 0; i < 32; i++) s += part[tid][i];
        s *= 0.088388347648318447f;
        if (base + tid >= NK) s = -1e30f;
        sc[tid] = s;
    }
    __syncthreads();
    if (tid < 64) red[tid] = fmaxf(sc[tid], sc[tid + 64]);
    __syncthreads();
    if (tid < 32) {
        float m = fmaxf(red[tid], red[tid + 32]);
        #pragma unroll
        for (int off = 16; off > 0; off >>= 1)
            m = fmaxf(m, __shfl_down_sync(0xffffffffu, m, off));
        if (tid == 0) red[0] = m;
    }
    __syncthreads();
    float mloc = red[0];
    __syncthreads();
    if (tid < 128) sc[tid] = expf(sc[tid] - mloc);
    __syncthreads();
    if (tid < 64) red[tid] = sc[tid] + sc[tid + 64];
    __syncthreads();
    if (tid < 32) {
        float s = red[tid] + red[tid + 32];
        #pragma unroll
        for (int off = 16; off > 0; off >>= 1)
            s += __shfl_down_sync(0xffffffffu, s, off);
        if (tid == 0) red[0] = s;
    }
    __syncthreads();
    float ssum = red[0];

    // ---- V phase ----
    float4 acc = make_float4(0.f, 0.f, 0.f, 0.f);
    #pragma unroll 4
    for (int i = 0; i < 16; i++) {
        int r = warp * 16 + i, k = base + r;
        if (k < NK) {
            const float* vr = kv_row(l, b, h, k, vh, vo, g_vscr);
            float4 v4 = ((const float4*)vr)[lane];
            float pr = sc[r];
            acc.x += pr * v4.x; acc.y += pr * v4.y;
            acc.z += pr * v4.z; acc.w += pr * v4.w;
        }
    }
    vred[warp][lane] = acc;
    __syncthreads();
    if (tid < 128) {
        int li = tid >> 2, c = tid & 3;
        float o = 0.f;
        #pragma unroll
        for (int w2 = 0; w2 < 8; w2++) o += ((const float*)&vred[w2][li])[c];
        g_po[blockIdx.x][bh][tid] = o;
    }
    if (tid == 0) { g_pm[blockIdx.x][bh] = mloc; g_ps[blockIdx.x][bh] = ssum; }

    // ---- last block for this (b,h) combines all 17 partials ----
    __threadfence();
    if (tid == 0) {
        unsigned int v = atomicAdd(&g_cnt[bh], 1u);
        is_last = (v == NCHUNK - 1);
    }
    __syncthreads();
    if (!is_last) return;
    __threadfence();                    // acquire partials from other blocks
    if (tid == 0) g_cnt[bh] = 0;        // reset for next layer / graph replay
    if (tid < 128) {
        float m = -1e30f;
        #pragma unroll
        for (int c = 0; c < NCHUNK; c++) m = fmaxf(m, g_pm[c][bh]);
        float S = 0.f, o = 0.f;
        #pragma unroll
        for (int c = 0; c < NCHUNK; c++) {
            float w = expf(g_pm[c][bh] - m);
            S += g_ps[c][bh] * w;
            o += g_po[c][bh][tid] * w;
        }
        g_x[b][h * DDIM + tid] += o / S;
    }
}

// ============================================================
// FFN
// ============================================================
__device__ __forceinline__ float gelu_exact(float x) {
    return 0.5f * x * (1.0f + erff(x * 0.70710678118654752f));
}

__global__ void k_ffn1(const float* __restrict__ w,
                       const float* __restrict__ gam, const float* __restrict__ bet, int l) {
    __shared__ __align__(16) float4 xs[1024];
    stage_ln(xs, gam, bet);
    int warp = threadIdx.x >> 5, lane = threadIdx.x & 31;
    int j = blockIdx.x * 8 + warp;
    const float4* w4 = (const float4*)(w + ((size_t)l * FFN + j) * HIDN);
    float2 r = dot2_smem<512>(w4, xs, lane);
    if (lane == 0) { g_h[0][j] = gelu_exact(r.x); g_h[1][j] = gelu_exact(r.y); }
}

__global__ void k_ffn2(const float* __restrict__ w, int l) {
    extern __shared__ float4 hs[];           // 4096 float4 = 64KB (both batches)
    const float4* hsrc = (const float4*)g_h[0];
    for (int i = threadIdx.x; i < 4096; i += 256) hs[i] = hsrc[i];
    __syncthreads();
    int warp = threadIdx.x >> 5, lane = threadIdx.x & 31;
    int j = blockIdx.x * 8 + warp;
    const float4* w4 = (const float4*)(w + ((size_t)l * HIDN + j) * FFN);
    float2 r = dot2_smem<2048>(w4, hs, lane);
    if (lane == 0) { g_x[0][j] += r.x; g_x[1][j] += r.y; }
}

// ============================================================
// LM head (LN fused) + final softmax
// ============================================================
__global__ void k_lmhead(const float* __restrict__ w,
                         const float* __restrict__ gam, const float* __restrict__ bet,
                         float* __restrict__ out) {
    __shared__ __align__(16) float4 xs[1024];
    stage_ln(xs, gam, bet);
    int warp = threadIdx.x >> 5, lane = threadIdx.x & 31;
    int j = blockIdx.x * 8 + warp;
    const float4* w4 = (const float4*)(w + (size_t)j * HIDN);
    float2 r = dot2_smem<512>(w4, xs, lane);
    if (lane == 0) { out[j] = r.x; out[(size_t)VV + j] = r.y; }
}

__global__ void k_softmax(float* __restrict__ out) {
    int b = blockIdx.x;
    float* o = out + (size_t)b * VV;
    int tid = threadIdx.x;               // 1024
    __shared__ float red[1024];
    float m = -1e30f;
    for (int i = tid; i < VV; i += 1024) m = fmaxf(m, o[i]);
    red[tid] = m; __syncthreads();
    for (int off = 512; off > 0; off >>= 1) { if (tid < off) red[tid] = fmaxf(red[tid], red[tid + off]); __syncthreads(); }
    float mb = red[0];
    __syncthreads();
    float s = 0.f;
    for (int i = tid; i < VV; i += 1024) s += expf(o[i] - mb);
    red[tid] = s; __syncthreads();
    for (int off = 512; off > 0; off >>= 1) { if (tid < off) red[tid] += red[tid + off]; __syncthreads(); }
    float inv = 1.0f / red[0];
    __syncthreads();
    for (int i = tid; i < VV; i += 1024) o[i] = expf(o[i] - mb) * inv;
}

// ============================================================
// launch (graph-capturable: kernel launches only)
// ============================================================
extern "C" void kernel_launch(void* const* d_in, const int* in_sizes, int n_in,
                              void* d_out, int out_size) {
    const float* x      = (const float*)d_in[0];
    const float* qkv_w  = (const float*)d_in[1];
    const float* ffn1_w = (const float*)d_in[2];
    const float* ffn2_w = (const float*)d_in[3];
    const float* out_w  = (const float*)d_in[4];
    const float* ln_g   = (const float*)d_in[5];
    const float* ln_b   = (const float*)d_in[6];
    const float* k_heap = (const float*)d_in[7];
    const float* v_heap = (const float*)d_in[8];
    const float* k_off  = (const float*)d_in[9];
    const float* v_off  = (const float*)d_in[10];
    const int*   pos    = (const int*)  d_in[11];
    float* out = (float*)d_out;

    cudaFuncSetAttribute(k_ffn2, cudaFuncAttributeMaxDynamicSharedMemorySize, 65536);

    k_init<<<BB, 256>>>(x, pos);

    for (int l = 0; l < LLN; l++) {
        k_qkv<<<768, 256>>>(qkv_w, ln_g, ln_b, l);
        { dim3 gs(NCHUNK, BB * NHH); k_flash<<<gs, 256>>>(k_heap, k_off, v_heap, v_off, l); }
        k_ffn1<<<1024, 256>>>(ffn1_w, ln_g, ln_b, l);
        k_ffn2<<<256, 256, 65536>>>(ffn2_w, l);
    }

    k_lmhead<<<4000, 256>>>(out_w, ln_g, ln_b, out);
    k_softmax<<<BB, 1024>>>(out);
}